// round 13
// baseline (speedup 1.0000x reference)
#include <cuda_runtime.h>

// Plenoxel forward: R=4096 rays, S=128 samples/ray, 160^3 grid.
// Block = 128 threads = 1 ray. Phase 1: density/alpha/global transmittance.
// Dedup + compact (coords,w) -> smem. Worker: 8 lanes per item, one corner-row
// per lane. Shifted-basis variants (O=0..3) PRECOMPUTED per ray in smem:
// worker reads bs via 3x LDS.128 instead of a 23-SEL tree per row.

#define GRES        160
#define NSAMP       128
#define T_NEAR      0.1f
#define T_FAR       10.0f
#define FULLMASK    0xffffffffu

__global__ __launch_bounds__(128, 8) void plenoxel_fwd_kernel(
    const float* __restrict__ ro,
    const float* __restrict__ rd,
    const float* __restrict__ density,
    const float* __restrict__ sh,
    float* __restrict__ out,
    int R)
{
    const float4* __restrict__ sh4 = (const float4*)sh;

    const int wir  = threadIdx.x >> 5;      // warp 0..3
    const int lane = threadIdx.x & 31;
    const int r    = blockIdx.x;             // one ray per block
    const int s    = threadIdx.x;             // sample 0..127

    __shared__ float sProd[4];
    __shared__ float sDep[4], sAcc[4];
    __shared__ float sWacc[4][3];
    __shared__ float sW[128];
    __shared__ float sVx[128], sVy[128], sVz[128];
    __shared__ int   sWarpCnt[4];
    __shared__ __align__(16) float sBS[4][12];   // shifted basis, one per O

    const float ox = ro[r*3+0], oy = ro[r*3+1], oz = ro[r*3+2];
    const float dx = rd[r*3+0], dy = rd[r*3+1], dz = rd[r*3+2];

    const float dnorm = sqrtf(dx*dx + dy*dy + dz*dz);
    const float inv   = 1.0f / (dnorm + 1e-8f);
    const float nx = dx*inv, ny = dy*inv, nz = dz*inv;

    float b[9];
    b[0] =  0.28209479177387814f;
    b[1] = -0.48860251190291987f * ny;
    b[2] =  0.48860251190291987f * nz;
    b[3] = -0.48860251190291987f * nx;
    b[4] =  1.0925484305920792f  * nx * ny;
    b[5] = -1.0925484305920792f  * ny * nz;
    b[6] =  0.31539156525252005f * (2.0f*nz*nz - nx*nx - ny*ny);
    b[7] = -1.0925484305920792f  * nx * nz;
    b[8] =  0.5462742152960396f  * (nx*nx - ny*ny);

    // Precompute sBS[O][k] = b[k-O] (0 outside [0,9)), one element per thread.
    if (threadIdx.x < 48) {
        const int O = threadIdx.x / 12;
        const int k = threadIdx.x % 12;
        const int j = k - O;
        float val = 0.0f;
        if (j >= 0 && j < 9) {
            switch (j) {
                case 0: val = b[0]; break;
                case 1: val = b[1]; break;
                case 2: val = b[2]; break;
                case 3: val = b[3]; break;
                case 4: val = b[4]; break;
                case 5: val = b[5]; break;
                case 6: val = b[6]; break;
                case 7: val = b[7]; break;
                default: val = b[8]; break;
            }
        }
        sBS[O][k] = val;
    }

    const float dt = (T_FAR - T_NEAR) / (float)(NSAMP - 1);
    const float t  = T_NEAR + dt * (float)s;

    float vx = (ox + t*dx + 1.0f) * 80.0f;
    float vy = (oy + t*dy + 1.0f) * 80.0f;
    float vz = (oz + t*dz + 1.0f) * 80.0f;
    vx = fminf(fmaxf(vx, 0.0f), 159.0f);
    vy = fminf(fmaxf(vy, 0.0f), 159.0f);
    vz = fminf(fmaxf(vz, 0.0f), 159.0f);

    const float fx = floorf(vx), fy = floorf(vy), fz = floorf(vz);
    const int x0 = (int)fx, y0 = (int)fy, z0 = (int)fz;
    const int x1 = min(x0 + 1, GRES - 1);
    const int y1 = min(y0 + 1, GRES - 1);
    const int z1 = min(z0 + 1, GRES - 1);
    const float ddx = vx - fx, ddy = vy - fy, ddz = vz - fz;
    const float wx0 = 1.0f - ddx, wx1 = ddx;
    const int   xd  = x1 - x0;

    // ---- Phase 1: density interp + alpha ----
    float dens;
    {
        const int  rz0 = z0 * GRES, rz1 = z1 * GRES;
        const int  i00 = (rz0 + y0) * GRES + x0;
        const int  i01 = (rz0 + y1) * GRES + x0;
        const int  i10 = (rz1 + y0) * GRES + x0;
        const int  i11 = (rz1 + y1) * GRES + x0;
        const float wz0 = 1.0f - ddz, wz1 = ddz;
        const float wy0 = 1.0f - ddy, wy1 = ddy;

        const float d000 = __ldg(density + i00),  d001 = __ldg(density + i00 + xd);
        const float d010 = __ldg(density + i01),  d011 = __ldg(density + i01 + xd);
        const float d100 = __ldg(density + i10),  d101 = __ldg(density + i10 + xd);
        const float d110 = __ldg(density + i11),  d111 = __ldg(density + i11 + xd);

        dens = wz0 * (wy0 * (wx0*d000 + wx1*d001) + wy1 * (wx0*d010 + wx1*d011))
             + wz1 * (wy0 * (wx0*d100 + wx1*d101) + wy1 * (wx0*d110 + wx1*d111));
    }

    const float dist  = ((s == NSAMP - 1) ? 1e10f : dt) * dnorm;
    const float alpha = 1.0f - __expf(-fmaxf(dens, 0.0f) * dist);

    // warp-local exclusive cumprod of (1 - alpha + 1e-10)
    float incl = 1.0f - alpha + 1e-10f;
    #pragma unroll
    for (int o = 1; o < 32; o <<= 1) {
        const float pv = __shfl_up_sync(FULLMASK, incl, o);
        if (lane >= o) incl *= pv;
    }
    float excl = __shfl_up_sync(FULLMASK, incl, 1);
    if (lane == 0) excl = 1.0f;
    const float warpProd = __shfl_sync(FULLMASK, incl, 31);

    if (lane == 0) sProd[wir] = warpProd;
    __syncthreads();

    float P = 1.0f;
    #pragma unroll
    for (int j = 0; j < 3; j++) if (j < wir) P *= sProd[j];
    const float w = alpha * excl * P;    // global weight

    // ---- depth/acc (all samples, fixed order) ----
    {
        float dep = w * t, acc = w;
        #pragma unroll
        for (int o = 16; o > 0; o >>= 1) {
            dep += __shfl_xor_sync(FULLMASK, dep, o);
            acc += __shfl_xor_sync(FULLMASK, acc, o);
        }
        if (lane == 0) { sDep[wir] = dep; sAcc[wir] = acc; }
    }

    // ---- Dedup identical-coord runs ----
    const float pvx = __shfl_up_sync(FULLMASK, vx, 1);
    const float pvy = __shfl_up_sync(FULLMASK, vy, 1);
    const float pvz = __shfl_up_sync(FULLMASK, vz, 1);
    const bool start = (lane == 0) || (vx != pvx) || (vy != pvy) || (vz != pvz);

    const unsigned sb      = __ballot_sync(FULLMASK, start);
    const unsigned mask_le = 0xffffffffu >> (31 - lane);
    const int      segid   = __popc(sb & mask_le);

    float wrun = w;
    #pragma unroll
    for (int o = 1; o < 32; o <<= 1) {
        const float wn = __shfl_down_sync(FULLMASK, wrun, o);
        const int   sn = __shfl_down_sync(FULLMASK, segid, o);
        if (lane + o < 32 && sn == segid) wrun += wn;
    }

    // ---- Compact: stash coords + folded weight ----
    const bool push = start && (wrun != 0.0f);
    const unsigned pb = __ballot_sync(FULLMASK, push);
    if (lane == 0) sWarpCnt[wir] = __popc(pb);
    __syncthreads();

    int base = 0, cnt = 0;
    #pragma unroll
    for (int j = 0; j < 4; j++) {
        if (j < wir) base += sWarpCnt[j];
        cnt += sWarpCnt[j];
    }
    if (push) {
        const unsigned mask_lt = mask_le ^ (1u << lane);
        const int pos = base + __popc(pb & mask_lt);
        sW[pos]  = wrun;
        sVx[pos] = vx;
        sVy[pos] = vy;
        sVz[pos] = vz;
    }
    __syncthreads();

    // ---- Worker: 8 lanes per item, one corner-row per lane ----
    float rgb0 = 0.f, rgb1 = 0.f, rgb2 = 0.f;
    const int sub = threadIdx.x & 7;
    const int px_ = sub & 1, py_ = (sub >> 1) & 1, pz_ = (sub >> 2) & 1;
    const int passes = (cnt + 15) >> 4;     // 16 items per pass (128/8)

    for (int p = 0; p < passes; p++) {
        const int it    = (p << 4) + (threadIdx.x >> 3);
        const bool valid = (it < cnt);

        float c0 = 0.f, c1 = 0.f, c2 = 0.f;
        float ww = 0.f;

        if (valid) {
            const float ux = sVx[it];
            const float uy = sVy[it];
            const float uz = sVz[it];
            ww = sW[it];

            const float gx = floorf(ux), gy = floorf(uy), gz = floorf(uz);
            const int a0  = (int)gx, b0i = (int)gy, c0i = (int)gz;
            const float ex = ux - gx, ey = uy - gy, ez = uz - gz;

            // this lane's corner
            const int xi = px_ ? min(a0  + 1, GRES - 1) : a0;
            const int yi = py_ ? min(b0i + 1, GRES - 1) : b0i;
            const int zi = pz_ ? min(c0i + 1, GRES - 1) : c0i;
            const float wc = (px_ ? ex : 1.0f - ex)
                           * (py_ ? ey : 1.0f - ey)
                           * (pz_ ? ez : 1.0f - ez);

            const int idx  = (zi * GRES + yi) * GRES + xi;
            const int F    = idx * 27;
            const int vbase = F >> 2;
            const int O    = F & 3;

            // batched row window (8 LDG.128, last predicated on O>=2)
            float v[32];
            #pragma unroll
            for (int i = 0; i < 7; i++) {
                const float4 q = __ldg(sh4 + vbase + i);
                v[4*i+0] = q.x; v[4*i+1] = q.y; v[4*i+2] = q.z; v[4*i+3] = q.w;
            }
            {
                float4 q = make_float4(0.f, 0.f, 0.f, 0.f);
                if (O >= 2) q = __ldg(sh4 + vbase + 7);
                v[28] = q.x; v[29] = q.y; v[30] = q.z; v[31] = q.w;
            }

            // shifted basis: 3x LDS.128 (replaces 23-SEL tree)
            const float4* bsp = reinterpret_cast<const float4*>(&sBS[O][0]);
            const float4 B0 = bsp[0];
            const float4 B1 = bsp[1];
            const float4 B2 = bsp[2];
            const float bs[12] = { B0.x, B0.y, B0.z, B0.w,
                                   B1.x, B1.y, B1.z, B1.w,
                                   B2.x, B2.y, B2.z, B2.w };

            float d0 = 0.f, d1 = 0.f, d2 = 0.f;
            #pragma unroll
            for (int k = 0; k < 12; k++) {
                const float bk = bs[k];
                d0 = fmaf(v[k],      bk, d0);
                d1 = fmaf(v[9 + k],  bk, d1);
                d2 = fmaf(v[18 + k], bk, d2);
            }
            c0 = wc * d0;
            c1 = wc * d1;
            c2 = wc * d2;
        }

        // combine the 8-lane group (fixed order: x, y, z)
        #pragma unroll
        for (int o = 1; o <= 4; o <<= 1) {
            c0 += __shfl_xor_sync(FULLMASK, c0, o);
            c1 += __shfl_xor_sync(FULLMASK, c1, o);
            c2 += __shfl_xor_sync(FULLMASK, c2, o);
        }

        if (valid && sub == 0) {
            const float col0 = __fdividef(1.0f, 1.0f + __expf(-c0));
            const float col1 = __fdividef(1.0f, 1.0f + __expf(-c1));
            const float col2 = __fdividef(1.0f, 1.0f + __expf(-c2));
            rgb0 = fmaf(ww, col0, rgb0);
            rgb1 = fmaf(ww, col1, rgb1);
            rgb2 = fmaf(ww, col2, rgb2);
        }
    }

    // fixed-order warp reduction of rgb partials
    #pragma unroll
    for (int o = 16; o > 0; o >>= 1) {
        rgb0 += __shfl_xor_sync(FULLMASK, rgb0, o);
        rgb1 += __shfl_xor_sync(FULLMASK, rgb1, o);
        rgb2 += __shfl_xor_sync(FULLMASK, rgb2, o);
    }
    if (lane == 0) {
        sWacc[wir][0] = rgb0;
        sWacc[wir][1] = rgb1;
        sWacc[wir][2] = rgb2;
    }
    __syncthreads();

    if (threadIdx.x == 0) {
        float o0 = 0.f, o1 = 0.f, o2 = 0.f, od = 0.f, oa = 0.f;
        #pragma unroll
        for (int j = 0; j < 4; j++) {
            o0 += sWacc[j][0];
            o1 += sWacc[j][1];
            o2 += sWacc[j][2];
            od += sDep[j];
            oa += sAcc[j];
        }
        out[r*3 + 0] = o0;
        out[r*3 + 1] = o1;
        out[r*3 + 2] = o2;
        out[R*3 + r] = od;
        out[R*4 + r] = oa;
    }
}

extern "C" void kernel_launch(void* const* d_in, const int* in_sizes, int n_in,
                              void* d_out, int out_size)
{
    const float* ro      = (const float*)d_in[0];
    const float* rd      = (const float*)d_in[1];
    const float* density = (const float*)d_in[2];
    const float* sh      = (const float*)d_in[3];
    float* out           = (float*)d_out;

    const int R = in_sizes[0] / 3;      // 4096 rays, 1 ray per 128-thread block
    plenoxel_fwd_kernel<<<R, 128>>>(ro, rd, density, sh, out, R);
}

// round 14
// speedup vs baseline: 1.1969x; 1.1969x over previous
#include <cuda_runtime.h>

// Plenoxel forward: R=4096 rays, S=128 samples/ray, 160^3 grid.
// Block = 128 threads = 1 ray. Phase 1: density/alpha/global transmittance.
// Dedup + compact (coords,w) -> smem. Worker: 8 lanes per item, one corner-row
// per lane; lanes whose trilinear corner weight is EXACTLY 0 (boundary-clamped
// samples) skip the entire row gather -> big L1-wavefront cut.

#define GRES        160
#define NSAMP       128
#define T_NEAR      0.1f
#define T_FAR       10.0f
#define FULLMASK    0xffffffffu

__global__ __launch_bounds__(128, 8) void plenoxel_fwd_kernel(
    const float* __restrict__ ro,
    const float* __restrict__ rd,
    const float* __restrict__ density,
    const float* __restrict__ sh,
    float* __restrict__ out,
    int R)
{
    const float4* __restrict__ sh4 = (const float4*)sh;

    const int wir  = threadIdx.x >> 5;      // warp 0..3
    const int lane = threadIdx.x & 31;
    const int r    = blockIdx.x;             // one ray per block
    const int s    = threadIdx.x;             // sample 0..127

    __shared__ float sProd[4];
    __shared__ float sDep[4], sAcc[4];
    __shared__ float sWacc[4][3];
    __shared__ float sW[128];
    __shared__ float sVx[128], sVy[128], sVz[128];
    __shared__ int   sWarpCnt[4];

    const float ox = ro[r*3+0], oy = ro[r*3+1], oz = ro[r*3+2];
    const float dx = rd[r*3+0], dy = rd[r*3+1], dz = rd[r*3+2];

    const float dnorm = sqrtf(dx*dx + dy*dy + dz*dz);
    const float inv   = 1.0f / (dnorm + 1e-8f);
    const float nx = dx*inv, ny = dy*inv, nz = dz*inv;

    float b[9];
    b[0] =  0.28209479177387814f;
    b[1] = -0.48860251190291987f * ny;
    b[2] =  0.48860251190291987f * nz;
    b[3] = -0.48860251190291987f * nx;
    b[4] =  1.0925484305920792f  * nx * ny;
    b[5] = -1.0925484305920792f  * ny * nz;
    b[6] =  0.31539156525252005f * (2.0f*nz*nz - nx*nx - ny*ny);
    b[7] = -1.0925484305920792f  * nx * nz;
    b[8] =  0.5462742152960396f  * (nx*nx - ny*ny);

    const float dt = (T_FAR - T_NEAR) / (float)(NSAMP - 1);
    const float t  = T_NEAR + dt * (float)s;

    float vx = (ox + t*dx + 1.0f) * 80.0f;
    float vy = (oy + t*dy + 1.0f) * 80.0f;
    float vz = (oz + t*dz + 1.0f) * 80.0f;
    vx = fminf(fmaxf(vx, 0.0f), 159.0f);
    vy = fminf(fmaxf(vy, 0.0f), 159.0f);
    vz = fminf(fmaxf(vz, 0.0f), 159.0f);

    const float fx = floorf(vx), fy = floorf(vy), fz = floorf(vz);
    const int x0 = (int)fx, y0 = (int)fy, z0 = (int)fz;
    const int x1 = min(x0 + 1, GRES - 1);
    const int y1 = min(y0 + 1, GRES - 1);
    const int z1 = min(z0 + 1, GRES - 1);
    const float ddx = vx - fx, ddy = vy - fy, ddz = vz - fz;
    const float wx0 = 1.0f - ddx, wx1 = ddx;
    const int   xd  = x1 - x0;

    // ---- Phase 1: density interp + alpha ----
    float dens;
    {
        const int  rz0 = z0 * GRES, rz1 = z1 * GRES;
        const int  i00 = (rz0 + y0) * GRES + x0;
        const int  i01 = (rz0 + y1) * GRES + x0;
        const int  i10 = (rz1 + y0) * GRES + x0;
        const int  i11 = (rz1 + y1) * GRES + x0;
        const float wz0 = 1.0f - ddz, wz1 = ddz;
        const float wy0 = 1.0f - ddy, wy1 = ddy;

        const float d000 = __ldg(density + i00),  d001 = __ldg(density + i00 + xd);
        const float d010 = __ldg(density + i01),  d011 = __ldg(density + i01 + xd);
        const float d100 = __ldg(density + i10),  d101 = __ldg(density + i10 + xd);
        const float d110 = __ldg(density + i11),  d111 = __ldg(density + i11 + xd);

        dens = wz0 * (wy0 * (wx0*d000 + wx1*d001) + wy1 * (wx0*d010 + wx1*d011))
             + wz1 * (wy0 * (wx0*d100 + wx1*d101) + wy1 * (wx0*d110 + wx1*d111));
    }

    const float dist  = ((s == NSAMP - 1) ? 1e10f : dt) * dnorm;
    const float alpha = 1.0f - __expf(-fmaxf(dens, 0.0f) * dist);

    // warp-local exclusive cumprod of (1 - alpha + 1e-10)
    float incl = 1.0f - alpha + 1e-10f;
    #pragma unroll
    for (int o = 1; o < 32; o <<= 1) {
        const float pv = __shfl_up_sync(FULLMASK, incl, o);
        if (lane >= o) incl *= pv;
    }
    float excl = __shfl_up_sync(FULLMASK, incl, 1);
    if (lane == 0) excl = 1.0f;
    const float warpProd = __shfl_sync(FULLMASK, incl, 31);

    if (lane == 0) sProd[wir] = warpProd;
    __syncthreads();

    float P = 1.0f;
    #pragma unroll
    for (int j = 0; j < 3; j++) if (j < wir) P *= sProd[j];
    const float w = alpha * excl * P;    // global weight

    // ---- depth/acc (all samples, fixed order) ----
    {
        float dep = w * t, acc = w;
        #pragma unroll
        for (int o = 16; o > 0; o >>= 1) {
            dep += __shfl_xor_sync(FULLMASK, dep, o);
            acc += __shfl_xor_sync(FULLMASK, acc, o);
        }
        if (lane == 0) { sDep[wir] = dep; sAcc[wir] = acc; }
    }

    // ---- Dedup identical-coord runs ----
    const float pvx = __shfl_up_sync(FULLMASK, vx, 1);
    const float pvy = __shfl_up_sync(FULLMASK, vy, 1);
    const float pvz = __shfl_up_sync(FULLMASK, vz, 1);
    const bool start = (lane == 0) || (vx != pvx) || (vy != pvy) || (vz != pvz);

    const unsigned sb      = __ballot_sync(FULLMASK, start);
    const unsigned mask_le = 0xffffffffu >> (31 - lane);
    const int      segid   = __popc(sb & mask_le);

    float wrun = w;
    #pragma unroll
    for (int o = 1; o < 32; o <<= 1) {
        const float wn = __shfl_down_sync(FULLMASK, wrun, o);
        const int   sn = __shfl_down_sync(FULLMASK, segid, o);
        if (lane + o < 32 && sn == segid) wrun += wn;
    }

    // ---- Compact: stash coords + folded weight ----
    const bool push = start && (wrun != 0.0f);
    const unsigned pb = __ballot_sync(FULLMASK, push);
    if (lane == 0) sWarpCnt[wir] = __popc(pb);
    __syncthreads();

    int base = 0, cnt = 0;
    #pragma unroll
    for (int j = 0; j < 4; j++) {
        if (j < wir) base += sWarpCnt[j];
        cnt += sWarpCnt[j];
    }
    if (push) {
        const unsigned mask_lt = mask_le ^ (1u << lane);
        const int pos = base + __popc(pb & mask_lt);
        sW[pos]  = wrun;
        sVx[pos] = vx;
        sVy[pos] = vy;
        sVz[pos] = vz;
    }
    __syncthreads();

    // ---- Worker: 8 lanes per item, one corner-row per lane ----
    float rgb0 = 0.f, rgb1 = 0.f, rgb2 = 0.f;
    const int sub = threadIdx.x & 7;
    const int px_ = sub & 1, py_ = (sub >> 1) & 1, pz_ = (sub >> 2) & 1;
    const int passes = (cnt + 15) >> 4;     // 16 items per pass (128/8)

    for (int p = 0; p < passes; p++) {
        const int it    = (p << 4) + (threadIdx.x >> 3);
        const bool valid = (it < cnt);

        float c0 = 0.f, c1 = 0.f, c2 = 0.f;
        float ww = 0.f;

        if (valid) {
            const float ux = sVx[it];
            const float uy = sVy[it];
            const float uz = sVz[it];
            ww = sW[it];

            const float gx = floorf(ux), gy = floorf(uy), gz = floorf(uz);
            const int a0  = (int)gx, b0i = (int)gy, c0i = (int)gz;
            const float ex = ux - gx, ey = uy - gy, ez = uz - gz;

            // this lane's corner weight; EXACTLY 0 for boundary-clamped axes
            const float wc = (px_ ? ex : 1.0f - ex)
                           * (py_ ? ey : 1.0f - ey)
                           * (pz_ ? ez : 1.0f - ez);

            if (wc != 0.0f) {
                const int xi = px_ ? min(a0  + 1, GRES - 1) : a0;
                const int yi = py_ ? min(b0i + 1, GRES - 1) : b0i;
                const int zi = pz_ ? min(c0i + 1, GRES - 1) : c0i;

                const int idx  = (zi * GRES + yi) * GRES + xi;
                const int F    = idx * 27;
                const int vbase = F >> 2;
                const int O    = F & 3;
                const bool s2  = (O & 2) != 0;
                const bool s1  = (O & 1) != 0;

                // batched row window (7 LDG.128 + predicated 8th)
                float v[32];
                #pragma unroll
                for (int i = 0; i < 7; i++) {
                    const float4 q = __ldg(sh4 + vbase + i);
                    v[4*i+0] = q.x; v[4*i+1] = q.y; v[4*i+2] = q.z; v[4*i+3] = q.w;
                }
                {
                    float4 q = make_float4(0.f, 0.f, 0.f, 0.f);
                    if (s2) q = __ldg(sh4 + vbase + 7);
                    v[28] = q.x; v[29] = q.y; v[30] = q.z; v[31] = q.w;
                }

                // shifted basis: bs[k] = b[k-O] (0 outside [0,9))
                float tt[12];
                tt[0]  = s2 ? 0.f  : b[0];
                tt[1]  = s2 ? 0.f  : b[1];
                #pragma unroll
                for (int k = 2; k <= 8; k++) tt[k] = s2 ? b[k-2] : b[k];
                tt[9]  = s2 ? b[7] : 0.f;
                tt[10] = s2 ? b[8] : 0.f;
                tt[11] = 0.f;

                float bs[12];
                bs[0] = s1 ? 0.f : tt[0];
                #pragma unroll
                for (int k = 1; k < 12; k++) bs[k] = s1 ? tt[k-1] : tt[k];

                float d0 = 0.f, d1 = 0.f, d2 = 0.f;
                #pragma unroll
                for (int k = 0; k < 12; k++) {
                    const float bk = bs[k];
                    d0 = fmaf(v[k],      bk, d0);
                    d1 = fmaf(v[9 + k],  bk, d1);
                    d2 = fmaf(v[18 + k], bk, d2);
                }
                c0 = wc * d0;
                c1 = wc * d1;
                c2 = wc * d2;
            }
        }

        // combine the 8-lane group (fixed order: x, y, z)
        #pragma unroll
        for (int o = 1; o <= 4; o <<= 1) {
            c0 += __shfl_xor_sync(FULLMASK, c0, o);
            c1 += __shfl_xor_sync(FULLMASK, c1, o);
            c2 += __shfl_xor_sync(FULLMASK, c2, o);
        }

        if (valid && sub == 0) {
            const float col0 = __fdividef(1.0f, 1.0f + __expf(-c0));
            const float col1 = __fdividef(1.0f, 1.0f + __expf(-c1));
            const float col2 = __fdividef(1.0f, 1.0f + __expf(-c2));
            rgb0 = fmaf(ww, col0, rgb0);
            rgb1 = fmaf(ww, col1, rgb1);
            rgb2 = fmaf(ww, col2, rgb2);
        }
    }

    // fixed-order warp reduction of rgb partials
    #pragma unroll
    for (int o = 16; o > 0; o >>= 1) {
        rgb0 += __shfl_xor_sync(FULLMASK, rgb0, o);
        rgb1 += __shfl_xor_sync(FULLMASK, rgb1, o);
        rgb2 += __shfl_xor_sync(FULLMASK, rgb2, o);
    }
    if (lane == 0) {
        sWacc[wir][0] = rgb0;
        sWacc[wir][1] = rgb1;
        sWacc[wir][2] = rgb2;
    }
    __syncthreads();

    if (threadIdx.x == 0) {
        float o0 = 0.f, o1 = 0.f, o2 = 0.f, od = 0.f, oa = 0.f;
        #pragma unroll
        for (int j = 0; j < 4; j++) {
            o0 += sWacc[j][0];
            o1 += sWacc[j][1];
            o2 += sWacc[j][2];
            od += sDep[j];
            oa += sAcc[j];
        }
        out[r*3 + 0] = o0;
        out[r*3 + 1] = o1;
        out[r*3 + 2] = o2;
        out[R*3 + r] = od;
        out[R*4 + r] = oa;
    }
}

extern "C" void kernel_launch(void* const* d_in, const int* in_sizes, int n_in,
                              void* d_out, int out_size)
{
    const float* ro      = (const float*)d_in[0];
    const float* rd      = (const float*)d_in[1];
    const float* density = (const float*)d_in[2];
    const float* sh      = (const float*)d_in[3];
    float* out           = (float*)d_out;

    const int R = in_sizes[0] / 3;      // 4096 rays, 1 ray per 128-thread block
    plenoxel_fwd_kernel<<<R, 128>>>(ro, rd, density, sh, out, R);
}